// round 9
// baseline (speedup 1.0000x reference)
#include <cuda_runtime.h>
#include <cuda_fp16.h>
#include <math.h>

#define W_IMG 2000
#define H_IMG 1500
#define HW_IMG (W_IMG * H_IMG)
#define NUM_VV 10
#define EPSF 1e-6f

// ---------------- global accumulators (zero at load; last block re-zeros) ---
__device__ double g_sim;
__device__ double g_norm;
__device__ double g_normz;
__device__ unsigned long long g_count;
__device__ unsigned int g_done;
__device__ float g_T[12];

// ---------------- repacked images: pixel-pair half layout -------------------
// entry (y, x) holds pixels (x, min(x+1, W-1)) of row y:
//   .x = (r0, g0)  .y = (b0, r1)  .z = (g1, b1)  .w = unused
__device__ uint4 g_p1[HW_IMG];
__device__ uint4 g_p2[HW_IMG];

// ---------------- register-only general 4x4 inverse (adjugate) --------------
__device__ __forceinline__ void inv4(const float m[16], float inv[16]) {
    inv[0] = m[5]*m[10]*m[15] - m[5]*m[11]*m[14] - m[9]*m[6]*m[15] + m[9]*m[7]*m[14] + m[13]*m[6]*m[11] - m[13]*m[7]*m[10];
    inv[4] = -m[4]*m[10]*m[15] + m[4]*m[11]*m[14] + m[8]*m[6]*m[15] - m[8]*m[7]*m[14] - m[12]*m[6]*m[11] + m[12]*m[7]*m[10];
    inv[8] = m[4]*m[9]*m[15] - m[4]*m[11]*m[13] - m[8]*m[5]*m[15] + m[8]*m[7]*m[13] + m[12]*m[5]*m[11] - m[12]*m[7]*m[9];
    inv[12] = -m[4]*m[9]*m[14] + m[4]*m[10]*m[13] + m[8]*m[5]*m[14] - m[8]*m[6]*m[13] - m[12]*m[5]*m[10] + m[12]*m[6]*m[9];
    inv[1] = -m[1]*m[10]*m[15] + m[1]*m[11]*m[14] + m[9]*m[2]*m[15] - m[9]*m[3]*m[14] - m[13]*m[2]*m[11] + m[13]*m[3]*m[10];
    inv[5] = m[0]*m[10]*m[15] - m[0]*m[11]*m[14] - m[8]*m[2]*m[15] + m[8]*m[3]*m[14] + m[12]*m[2]*m[11] - m[12]*m[3]*m[10];
    inv[9] = -m[0]*m[9]*m[15] + m[0]*m[11]*m[13] + m[8]*m[1]*m[15] - m[8]*m[3]*m[13] - m[12]*m[1]*m[11] + m[12]*m[3]*m[9];
    inv[13] = m[0]*m[9]*m[14] - m[0]*m[10]*m[13] - m[8]*m[1]*m[14] + m[8]*m[2]*m[13] + m[12]*m[1]*m[10] - m[12]*m[2]*m[9];
    inv[2] = m[1]*m[6]*m[15] - m[1]*m[7]*m[14] - m[5]*m[2]*m[15] + m[5]*m[3]*m[14] + m[13]*m[2]*m[7] - m[13]*m[3]*m[6];
    inv[6] = -m[0]*m[6]*m[15] + m[0]*m[7]*m[14] + m[4]*m[2]*m[15] - m[4]*m[3]*m[14] - m[12]*m[2]*m[7] + m[12]*m[3]*m[6];
    inv[10] = m[0]*m[5]*m[15] - m[0]*m[7]*m[13] - m[4]*m[1]*m[15] + m[4]*m[3]*m[13] + m[12]*m[1]*m[7] - m[12]*m[3]*m[5];
    inv[14] = -m[0]*m[5]*m[14] + m[0]*m[6]*m[13] + m[4]*m[1]*m[14] - m[4]*m[2]*m[13] - m[12]*m[1]*m[6] + m[12]*m[2]*m[5];
    inv[3] = -m[1]*m[6]*m[11] + m[1]*m[7]*m[10] + m[5]*m[2]*m[11] - m[5]*m[3]*m[10] - m[9]*m[2]*m[7] + m[9]*m[3]*m[6];
    inv[7] = m[0]*m[6]*m[11] - m[0]*m[7]*m[10] - m[4]*m[2]*m[11] + m[4]*m[3]*m[10] + m[8]*m[2]*m[7] - m[8]*m[3]*m[6];
    inv[11] = -m[0]*m[5]*m[11] + m[0]*m[7]*m[9] + m[4]*m[1]*m[11] - m[4]*m[3]*m[9] - m[8]*m[1]*m[7] + m[8]*m[3]*m[5];
    inv[15] = m[0]*m[5]*m[10] - m[0]*m[6]*m[9] - m[4]*m[1]*m[10] + m[4]*m[2]*m[9] + m[8]*m[1]*m[6] - m[8]*m[2]*m[5];
    float det = m[0]*inv[0] + m[1]*inv[4] + m[2]*inv[8] + m[3]*inv[12];
    float rd = 1.0f / det;
    #pragma unroll
    for (int i = 0; i < 16; i++) inv[i] *= rd;
}

// ---------------- repack kernel (also builds T once) -------------------------
__global__ void repack_k(const float* __restrict__ rgb1,
                         const float* __restrict__ rgb2,
                         const float* __restrict__ K2,
                         const float* __restrict__ E1,
                         const float* __restrict__ E2) {
    if (blockIdx.x == 0 && threadIdx.x == 0) {
        float m[16], iv[16];
        #pragma unroll
        for (int i = 0; i < 16; i++) m[i] = E1[i];
        inv4(m, iv);
        float Mm[12];
        #pragma unroll
        for (int i = 0; i < 3; i++)
            #pragma unroll
            for (int j = 0; j < 4; j++) {
                float s = 0.0f;
                #pragma unroll
                for (int k = 0; k < 4; k++) s += E2[i * 4 + k] * iv[k * 4 + j];
                Mm[i * 4 + j] = s;
            }
        #pragma unroll
        for (int i = 0; i < 3; i++)
            #pragma unroll
            for (int j = 0; j < 4; j++) {
                float s = 0.0f;
                #pragma unroll
                for (int k = 0; k < 3; k++) s += K2[i * 3 + k] * Mm[k * 4 + j];
                g_T[i * 4 + j] = s;
            }
    }

    int idx = blockIdx.x * blockDim.x + threadIdx.x;
    int stride = gridDim.x * blockDim.x;
    for (int i = idx; i < HW_IMG; i += stride) {
        int x = i % W_IMG;
        int ip1 = (x < W_IMG - 1) ? i + 1 : i;

        float r0 = rgb1[i],           gg0 = rgb1[HW_IMG + i],   b0 = rgb1[2 * HW_IMG + i];
        float r1 = rgb1[ip1],         gg1 = rgb1[HW_IMG + ip1], b1 = rgb1[2 * HW_IMG + ip1];
        uint4 v;
        __half2 h0 = __floats2half2_rn(r0, gg0);
        __half2 h1 = __floats2half2_rn(b0, r1);
        __half2 h2 = __floats2half2_rn(gg1, b1);
        v.x = *(unsigned int*)&h0;
        v.y = *(unsigned int*)&h1;
        v.z = *(unsigned int*)&h2;
        v.w = 0u;
        g_p1[i] = v;

        r0 = rgb2[i];   gg0 = rgb2[HW_IMG + i];   b0 = rgb2[2 * HW_IMG + i];
        r1 = rgb2[ip1]; gg1 = rgb2[HW_IMG + ip1]; b1 = rgb2[2 * HW_IMG + ip1];
        h0 = __floats2half2_rn(r0, gg0);
        h1 = __floats2half2_rn(b0, r1);
        h2 = __floats2half2_rn(gg1, b1);
        v.x = *(unsigned int*)&h0;
        v.y = *(unsigned int*)&h1;
        v.z = *(unsigned int*)&h2;
        v.w = 0u;
        g_p2[i] = v;
    }
}

// ---------------- bilinear 3-channel sample from pixel pairs ----------------
__device__ __forceinline__ void sample3p(const uint4* __restrict__ img, float u, float v,
                                         float& c0, float& c1, float& c2) {
    float x = u * (float)(W_IMG - 1);
    float y = v * (float)(H_IMG - 1);
    float xf = floorf(x), yf = floorf(y);
    int x0 = (int)xf, y0 = (int)yf;
    int y1 = min(y0 + 1, H_IMG - 1);
    float wx = x - xf, wy = y - yf;

    uint4 qa = img[y0 * W_IMG + x0];   // row y0: pixels x0, x0+1
    uint4 qb = img[y1 * W_IMG + x0];   // row y1

    float2 a0 = __half22float2(*(__half2*)&qa.x);  // r0 g0
    float2 a1 = __half22float2(*(__half2*)&qa.y);  // b0 r1
    float2 a2 = __half22float2(*(__half2*)&qa.z);  // g1 b1
    float2 b0 = __half22float2(*(__half2*)&qb.x);
    float2 b1 = __half22float2(*(__half2*)&qb.y);
    float2 b2 = __half22float2(*(__half2*)&qb.z);

    // horizontal lerp per row, then vertical lerp
    float tr = a0.x + wx * (a1.y - a0.x);
    float tg = a0.y + wx * (a2.x - a0.y);
    float tb = a1.x + wx * (a2.y - a1.x);
    float br = b0.x + wx * (b1.y - b0.x);
    float bg = b0.y + wx * (b2.x - b0.y);
    float bb = b1.x + wx * (b2.y - b1.x);
    c0 = tr + wy * (br - tr);
    c1 = tg + wy * (bg - tg);
    c2 = tb + wy * (bb - tb);
}

__device__ __forceinline__ float clamp_uv(float q) {
    return fminf(fmaxf(q, 0.0f), 0.999999f);
}

// ---------------- main per-edge kernel ---------------------------------------
__global__ __launch_bounds__(128) void edge_k(const float* __restrict__ ep,
                                              const float* __restrict__ K1,
                                              float* __restrict__ out,
                                              int N) {
    int e = blockIdx.x;
    if (e >= N) return;

    const float* p = ep + (size_t)e * 12;
    float p0x = p[0],  p0y = p[1],  p0z = p[2];
    float p1x = p[3],  p1y = p[4],  p1z = p[5];
    float p2x = p[6],  p2y = p[7],  p2z = p[8];
    float p3x = p[9],  p3y = p[10], p3z = p[11];

    float cdx = p1x - p0x, cdy = p1y - p0y, cdz = p1z - p0z;
    float ndx = p3x - p1x, ndy = p3y - p1y, ndz = p3z - p1z;

    float ax = cdx + EPSF, ay = cdy + EPSF, az = cdz + EPSF;
    float cur_len = sqrtf(ax * ax + ay * ay + az * az);
    float inv_len = 1.0f / cur_len;
    float dx = cdx * inv_len, dy_ = cdy * inv_len, dz = cdz * inv_len;

    float cnx = dy_ * ndz - dz * ndy;
    float cny = dz * ndx - dx * ndz;
    float cnz = dx * ndy - dy_ * ndx;
    {
        float nn = sqrtf(cnx * cnx + cny * cny + cnz * cnz) + EPSF;
        cnx /= nn; cny /= nn; cnz /= nn;
    }
    if (cnz > 0.0f) { cnx = -cnx; cny = -cny; cnz = -cnz; }

    float cux = cny * dz - cnz * dy_;
    float cuy = cnz * dx - cnx * dz;
    float cuz = cnx * dy_ - cny * dx;
    {
        float nn = sqrtf(cux * cux + cuy * cuy + cuz * cuz) + EPSF;
        cux /= nn; cuy /= nn; cuz /= nn;
    }

    int num_h = (int)floorf(cur_len / 0.05f);
    num_h = max(2, min(1000, num_h));

    if (threadIdx.x == 0) {
        float pdx = p0x - p2x, pdy = p0y - p2y, pdz = p0z - p2z;
        float pnx = pdy * dz - pdz * dy_;
        float pny = pdz * dx - pdx * dz;
        float pnz = pdx * dy_ - pdy * dx;
        float nn = sqrtf(pnx * pnx + pny * pny + pnz * pnz) + EPSF;
        float nl = 1.0f - (cnx * pnx + cny * pny + cnz * pnz) / nn;

        float onx = p0y * p1z - p0z * p1y;
        float ony = p0z * p1x - p0x * p1z;
        float onz = p0x * p1y - p0y * p1x;
        float on = sqrtf(onx * onx + ony * ony + onz * onz) + EPSF;
        float snp = fminf(fabsf((cux * onx + cuy * ony + cuz * onz) / on), 0.5f);
        float nz = 1.0f - snp / 0.5f;

        atomicAdd(&g_norm, (double)nl);
        atomicAdd(&g_normz, (double)nz);
        atomicAdd(&g_count, (unsigned long long)num_h);
    }

    float k00 = K1[0], k01 = K1[1], k02 = K1[2];
    float k10 = K1[3], k11 = K1[4], k12 = K1[5];
    float k20 = K1[6], k21 = K1[7], k22 = K1[8];
    float t00 = g_T[0],  t01 = g_T[1],  t02 = g_T[2],  t03 = g_T[3];
    float t10 = g_T[4],  t11 = g_T[5],  t12 = g_T[6],  t13 = g_T[7];
    float t20 = g_T[8],  t21 = g_T[9],  t22 = g_T[10], t23 = g_T[11];

    float step = cur_len / (float)(num_h - 1);
    int total = num_h * NUM_VV;
    double lsim = 0.0;

    for (int i = threadIdx.x; i < total; i += 128) {
        int px = i / NUM_VV;
        int dv = i - px * NUM_VV;
        float cx = (float)px * step;
        float cy = (float)dv * (0.5f / 9.0f);

        float ptx = dx * cx + cux * cy + p0x;
        float pty = dy_ * cx + cuy * cy + p0y;
        float ptz = dz * cx + cuz * cy + p0z;

        float z1 = k20 * ptx + k21 * pty + k22 * ptz;
        float u1 = clamp_uv((k00 * ptx + k01 * pty + k02 * ptz) / z1);
        float v1 = clamp_uv((k10 * ptx + k11 * pty + k12 * ptz) / z1);
        float s1a, s1b, s1c;
        sample3p(g_p1, u1, v1, s1a, s1b, s1c);

        float z2 = t20 * ptx + t21 * pty + t22 * ptz + t23;
        float u2 = clamp_uv((t00 * ptx + t01 * pty + t02 * ptz + t03) / z2);
        float v2 = clamp_uv((t10 * ptx + t11 * pty + t12 * ptz + t13) / z2);
        float s2a, s2b, s2c;
        sample3p(g_p2, u2, v2, s2a, s2b, s2c);

        float d0 = s1a - s2a, d1 = s1b - s2b, d2 = s1c - s2c;
        lsim += (double)(d0 * d0 + d1 * d1 + d2 * d2);
    }

    // block reduction
    for (int o = 16; o > 0; o >>= 1)
        lsim += __shfl_down_sync(0xffffffffu, lsim, o);
    __shared__ double ssum[4];
    int lane = threadIdx.x & 31;
    int w = threadIdx.x >> 5;
    if (lane == 0) ssum[w] = lsim;
    __syncthreads();
    if (threadIdx.x == 0) {
        double t = ssum[0] + ssum[1] + ssum[2] + ssum[3];
        atomicAdd(&g_sim, t);

        // last-block finalize
        __threadfence();
        unsigned int done = atomicAdd(&g_done, 1u);
        if (done == (unsigned int)gridDim.x - 1u) {
            double sim = g_sim, nrm = g_norm, nrz = g_normz;
            double cnt = (double)g_count * (double)NUM_VV * 3.0;
            out[0] = (float)(sim / cnt);
            out[1] = (float)(nrm / (double)N * 0.5);
            out[2] = (float)(nrz / (double)N);
            g_sim = 0.0; g_norm = 0.0; g_normz = 0.0;
            g_count = 0ull; g_done = 0u;
        }
    }
}

// ---------------- launch -------------------------------------------------------
extern "C" void kernel_launch(void* const* d_in, const int* in_sizes, int n_in,
                              void* d_out, int out_size) {
    const float* ep   = (const float*)d_in[0];
    const float* K1   = (const float*)d_in[1];
    const float* K2   = (const float*)d_in[2];
    const float* E1   = (const float*)d_in[3];
    const float* E2   = (const float*)d_in[4];
    const float* rgb1 = (const float*)d_in[5];
    const float* rgb2 = (const float*)d_in[6];
    float* out = (float*)d_out;

    int N = in_sizes[0] / 12;

    repack_k<<<2048, 256>>>(rgb1, rgb2, K2, E1, E2);
    edge_k<<<N, 128>>>(ep, K1, out, N);
}

// round 10
// speedup vs baseline: 1.2000x; 1.2000x over previous
#include <cuda_runtime.h>
#include <math.h>

#define W_IMG 2000
#define H_IMG 1500
#define HW_IMG (W_IMG * H_IMG)
#define NUM_VV 10
#define EPSF 1e-6f

// ---------------- global accumulators (zero at load; last block re-zeros) ---
__device__ double g_sim;
__device__ double g_norm;
__device__ double g_normz;
__device__ unsigned long long g_count;
__device__ unsigned int g_done;
__device__ float g_T[12];

// ---------------- repacked images: pixel-pair u8 layout ---------------------
// entry (y, x): bytes [r0 g0 b0 r1 | g1 b1 0 0] for pixels (x, min(x+1,W-1))
__device__ uint2 g_p1[HW_IMG];
__device__ uint2 g_p2[HW_IMG];

// ---------------- register-only general 4x4 inverse (adjugate) --------------
__device__ __forceinline__ void inv4(const float m[16], float inv[16]) {
    inv[0] = m[5]*m[10]*m[15] - m[5]*m[11]*m[14] - m[9]*m[6]*m[15] + m[9]*m[7]*m[14] + m[13]*m[6]*m[11] - m[13]*m[7]*m[10];
    inv[4] = -m[4]*m[10]*m[15] + m[4]*m[11]*m[14] + m[8]*m[6]*m[15] - m[8]*m[7]*m[14] - m[12]*m[6]*m[11] + m[12]*m[7]*m[10];
    inv[8] = m[4]*m[9]*m[15] - m[4]*m[11]*m[13] - m[8]*m[5]*m[15] + m[8]*m[7]*m[13] + m[12]*m[5]*m[11] - m[12]*m[7]*m[9];
    inv[12] = -m[4]*m[9]*m[14] + m[4]*m[10]*m[13] + m[8]*m[5]*m[14] - m[8]*m[6]*m[13] - m[12]*m[5]*m[10] + m[12]*m[6]*m[9];
    inv[1] = -m[1]*m[10]*m[15] + m[1]*m[11]*m[14] + m[9]*m[2]*m[15] - m[9]*m[3]*m[14] - m[13]*m[2]*m[11] + m[13]*m[3]*m[10];
    inv[5] = m[0]*m[10]*m[15] - m[0]*m[11]*m[14] - m[8]*m[2]*m[15] + m[8]*m[3]*m[14] + m[12]*m[2]*m[11] - m[12]*m[3]*m[10];
    inv[9] = -m[0]*m[9]*m[15] + m[0]*m[11]*m[13] + m[8]*m[1]*m[15] - m[8]*m[3]*m[13] - m[12]*m[1]*m[11] + m[12]*m[3]*m[9];
    inv[13] = m[0]*m[9]*m[14] - m[0]*m[10]*m[13] - m[8]*m[1]*m[14] + m[8]*m[2]*m[13] + m[12]*m[1]*m[10] - m[12]*m[2]*m[9];
    inv[2] = m[1]*m[6]*m[15] - m[1]*m[7]*m[14] - m[5]*m[2]*m[15] + m[5]*m[3]*m[14] + m[13]*m[2]*m[7] - m[13]*m[3]*m[6];
    inv[6] = -m[0]*m[6]*m[15] + m[0]*m[7]*m[14] + m[4]*m[2]*m[15] - m[4]*m[3]*m[14] - m[12]*m[2]*m[7] + m[12]*m[3]*m[6];
    inv[10] = m[0]*m[5]*m[15] - m[0]*m[7]*m[13] - m[4]*m[1]*m[15] + m[4]*m[3]*m[13] + m[12]*m[1]*m[7] - m[12]*m[3]*m[5];
    inv[14] = -m[0]*m[5]*m[14] + m[0]*m[6]*m[13] + m[4]*m[1]*m[14] - m[4]*m[2]*m[13] - m[12]*m[1]*m[6] + m[12]*m[2]*m[5];
    inv[3] = -m[1]*m[6]*m[11] + m[1]*m[7]*m[10] + m[5]*m[2]*m[11] - m[5]*m[3]*m[10] - m[9]*m[2]*m[7] + m[9]*m[3]*m[6];
    inv[7] = m[0]*m[6]*m[11] - m[0]*m[7]*m[10] - m[4]*m[2]*m[11] + m[4]*m[3]*m[10] + m[8]*m[2]*m[7] - m[8]*m[3]*m[6];
    inv[11] = -m[0]*m[5]*m[11] + m[0]*m[7]*m[9] + m[4]*m[1]*m[11] - m[4]*m[3]*m[9] - m[8]*m[1]*m[7] + m[8]*m[3]*m[5];
    inv[15] = m[0]*m[5]*m[10] - m[0]*m[6]*m[9] - m[4]*m[1]*m[10] + m[4]*m[2]*m[9] + m[8]*m[1]*m[6] - m[8]*m[2]*m[5];
    float det = m[0]*inv[0] + m[1]*inv[4] + m[2]*inv[8] + m[3]*inv[12];
    float rd = 1.0f / det;
    #pragma unroll
    for (int i = 0; i < 16; i++) inv[i] *= rd;
}

// ---------------- repack kernel (also builds T once) -------------------------
__global__ void repack_k(const float* __restrict__ rgb1,
                         const float* __restrict__ rgb2,
                         const float* __restrict__ K2,
                         const float* __restrict__ E1,
                         const float* __restrict__ E2) {
    if (blockIdx.x == 0 && threadIdx.x == 0) {
        float m[16], iv[16];
        #pragma unroll
        for (int i = 0; i < 16; i++) m[i] = E1[i];
        inv4(m, iv);
        float Mm[12];
        #pragma unroll
        for (int i = 0; i < 3; i++)
            #pragma unroll
            for (int j = 0; j < 4; j++) {
                float s = 0.0f;
                #pragma unroll
                for (int k = 0; k < 4; k++) s += E2[i * 4 + k] * iv[k * 4 + j];
                Mm[i * 4 + j] = s;
            }
        #pragma unroll
        for (int i = 0; i < 3; i++)
            #pragma unroll
            for (int j = 0; j < 4; j++) {
                float s = 0.0f;
                #pragma unroll
                for (int k = 0; k < 3; k++) s += K2[i * 3 + k] * Mm[k * 4 + j];
                g_T[i * 4 + j] = s;
            }
    }

    int idx = blockIdx.x * blockDim.x + threadIdx.x;
    int stride = gridDim.x * blockDim.x;
    for (int i = idx; i < HW_IMG; i += stride) {
        int x = i % W_IMG;
        int ip1 = (x < W_IMG - 1) ? i + 1 : i;

        unsigned int r0 = __float2uint_rn(rgb1[i] * 255.0f);
        unsigned int gg0 = __float2uint_rn(rgb1[HW_IMG + i] * 255.0f);
        unsigned int b0 = __float2uint_rn(rgb1[2 * HW_IMG + i] * 255.0f);
        unsigned int r1 = __float2uint_rn(rgb1[ip1] * 255.0f);
        unsigned int gg1 = __float2uint_rn(rgb1[HW_IMG + ip1] * 255.0f);
        unsigned int b1 = __float2uint_rn(rgb1[2 * HW_IMG + ip1] * 255.0f);
        uint2 v;
        v.x = r0 | (gg0 << 8) | (b0 << 16) | (r1 << 24);
        v.y = gg1 | (b1 << 8);
        g_p1[i] = v;

        r0 = __float2uint_rn(rgb2[i] * 255.0f);
        gg0 = __float2uint_rn(rgb2[HW_IMG + i] * 255.0f);
        b0 = __float2uint_rn(rgb2[2 * HW_IMG + i] * 255.0f);
        r1 = __float2uint_rn(rgb2[ip1] * 255.0f);
        gg1 = __float2uint_rn(rgb2[HW_IMG + ip1] * 255.0f);
        b1 = __float2uint_rn(rgb2[2 * HW_IMG + ip1] * 255.0f);
        v.x = r0 | (gg0 << 8) | (b0 << 16) | (r1 << 24);
        v.y = gg1 | (b1 << 8);
        g_p2[i] = v;
    }
}

// ---------------- bilinear 3-channel sample from u8 pixel pairs -------------
__device__ __forceinline__ void sample3u(const uint2* __restrict__ img, float u, float v,
                                         float& c0, float& c1, float& c2) {
    float x = u * (float)(W_IMG - 1);
    float y = v * (float)(H_IMG - 1);
    float xf = floorf(x), yf = floorf(y);
    int x0 = (int)xf, y0 = (int)yf;
    int y1 = min(y0 + 1, H_IMG - 1);
    float wx = x - xf, wy = y - yf;

    uint2 qa = img[y0 * W_IMG + x0];   // row y0: pixels x0, x0+1
    uint2 qb = img[y1 * W_IMG + x0];   // row y1

    float ar0 = (float)(qa.x & 0xffu);
    float ag0 = (float)((qa.x >> 8) & 0xffu);
    float ab0 = (float)((qa.x >> 16) & 0xffu);
    float ar1 = (float)(qa.x >> 24);
    float ag1 = (float)(qa.y & 0xffu);
    float ab1 = (float)((qa.y >> 8) & 0xffu);

    float br0 = (float)(qb.x & 0xffu);
    float bg0 = (float)((qb.x >> 8) & 0xffu);
    float bb0 = (float)((qb.x >> 16) & 0xffu);
    float br1 = (float)(qb.x >> 24);
    float bg1 = (float)(qb.y & 0xffu);
    float bb1 = (float)((qb.y >> 8) & 0xffu);

    // horizontal lerp per row, vertical lerp, scale 1/255 at the end
    float tr = ar0 + wx * (ar1 - ar0);
    float tg = ag0 + wx * (ag1 - ag0);
    float tb = ab0 + wx * (ab1 - ab0);
    float br = br0 + wx * (br1 - br0);
    float bg = bg0 + wx * (bg1 - bg0);
    float bb = bb0 + wx * (bb1 - bb0);
    c0 = (tr + wy * (br - tr)) * (1.0f / 255.0f);
    c1 = (tg + wy * (bg - tg)) * (1.0f / 255.0f);
    c2 = (tb + wy * (bb - tb)) * (1.0f / 255.0f);
}

__device__ __forceinline__ float clamp_uv(float q) {
    return fminf(fmaxf(q, 0.0f), 0.999999f);
}

// ---------------- main per-edge kernel ---------------------------------------
__global__ __launch_bounds__(128) void edge_k(const float* __restrict__ ep,
                                              const float* __restrict__ K1,
                                              float* __restrict__ out,
                                              int N) {
    int e = blockIdx.x;
    if (e >= N) return;

    const float* p = ep + (size_t)e * 12;
    float p0x = p[0],  p0y = p[1],  p0z = p[2];
    float p1x = p[3],  p1y = p[4],  p1z = p[5];
    float p2x = p[6],  p2y = p[7],  p2z = p[8];
    float p3x = p[9],  p3y = p[10], p3z = p[11];

    float cdx = p1x - p0x, cdy = p1y - p0y, cdz = p1z - p0z;
    float ndx = p3x - p1x, ndy = p3y - p1y, ndz = p3z - p1z;

    float ax = cdx + EPSF, ay = cdy + EPSF, az = cdz + EPSF;
    float cur_len = sqrtf(ax * ax + ay * ay + az * az);
    float inv_len = 1.0f / cur_len;
    float dx = cdx * inv_len, dy_ = cdy * inv_len, dz = cdz * inv_len;

    float cnx = dy_ * ndz - dz * ndy;
    float cny = dz * ndx - dx * ndz;
    float cnz = dx * ndy - dy_ * ndx;
    {
        float nn = sqrtf(cnx * cnx + cny * cny + cnz * cnz) + EPSF;
        cnx /= nn; cny /= nn; cnz /= nn;
    }
    if (cnz > 0.0f) { cnx = -cnx; cny = -cny; cnz = -cnz; }

    float cux = cny * dz - cnz * dy_;
    float cuy = cnz * dx - cnx * dz;
    float cuz = cnx * dy_ - cny * dx;
    {
        float nn = sqrtf(cux * cux + cuy * cuy + cuz * cuz) + EPSF;
        cux /= nn; cuy /= nn; cuz /= nn;
    }

    int num_h = (int)floorf(cur_len / 0.05f);
    num_h = max(2, min(1000, num_h));

    if (threadIdx.x == 0) {
        float pdx = p0x - p2x, pdy = p0y - p2y, pdz = p0z - p2z;
        float pnx = pdy * dz - pdz * dy_;
        float pny = pdz * dx - pdx * dz;
        float pnz = pdx * dy_ - pdy * dx;
        float nn = sqrtf(pnx * pnx + pny * pny + pnz * pnz) + EPSF;
        float nl = 1.0f - (cnx * pnx + cny * pny + cnz * pnz) / nn;

        float onx = p0y * p1z - p0z * p1y;
        float ony = p0z * p1x - p0x * p1z;
        float onz = p0x * p1y - p0y * p1x;
        float on = sqrtf(onx * onx + ony * ony + onz * onz) + EPSF;
        float snp = fminf(fabsf((cux * onx + cuy * ony + cuz * onz) / on), 0.5f);
        float nz = 1.0f - snp / 0.5f;

        atomicAdd(&g_norm, (double)nl);
        atomicAdd(&g_normz, (double)nz);
        atomicAdd(&g_count, (unsigned long long)num_h);
    }

    float k00 = K1[0], k01 = K1[1], k02 = K1[2];
    float k10 = K1[3], k11 = K1[4], k12 = K1[5];
    float k20 = K1[6], k21 = K1[7], k22 = K1[8];
    float t00 = g_T[0],  t01 = g_T[1],  t02 = g_T[2],  t03 = g_T[3];
    float t10 = g_T[4],  t11 = g_T[5],  t12 = g_T[6],  t13 = g_T[7];
    float t20 = g_T[8],  t21 = g_T[9],  t22 = g_T[10], t23 = g_T[11];

    float step = cur_len / (float)(num_h - 1);
    int total = num_h * NUM_VV;
    double lsim = 0.0;

    for (int i = threadIdx.x; i < total; i += 128) {
        int px = i / NUM_VV;
        int dv = i - px * NUM_VV;
        float cx = (float)px * step;
        float cy = (float)dv * (0.5f / 9.0f);

        float ptx = dx * cx + cux * cy + p0x;
        float pty = dy_ * cx + cuy * cy + p0y;
        float ptz = dz * cx + cuz * cy + p0z;

        float z1 = k20 * ptx + k21 * pty + k22 * ptz;
        float u1 = clamp_uv((k00 * ptx + k01 * pty + k02 * ptz) / z1);
        float v1 = clamp_uv((k10 * ptx + k11 * pty + k12 * ptz) / z1);
        float s1a, s1b, s1c;
        sample3u(g_p1, u1, v1, s1a, s1b, s1c);

        float z2 = t20 * ptx + t21 * pty + t22 * ptz + t23;
        float u2 = clamp_uv((t00 * ptx + t01 * pty + t02 * ptz + t03) / z2);
        float v2 = clamp_uv((t10 * ptx + t11 * pty + t12 * ptz + t13) / z2);
        float s2a, s2b, s2c;
        sample3u(g_p2, u2, v2, s2a, s2b, s2c);

        float d0 = s1a - s2a, d1 = s1b - s2b, d2 = s1c - s2c;
        lsim += (double)(d0 * d0 + d1 * d1 + d2 * d2);
    }

    // block reduction
    for (int o = 16; o > 0; o >>= 1)
        lsim += __shfl_down_sync(0xffffffffu, lsim, o);
    __shared__ double ssum[4];
    int lane = threadIdx.x & 31;
    int w = threadIdx.x >> 5;
    if (lane == 0) ssum[w] = lsim;
    __syncthreads();
    if (threadIdx.x == 0) {
        double t = ssum[0] + ssum[1] + ssum[2] + ssum[3];
        atomicAdd(&g_sim, t);

        // last-block finalize
        __threadfence();
        unsigned int done = atomicAdd(&g_done, 1u);
        if (done == (unsigned int)gridDim.x - 1u) {
            double sim = g_sim, nrm = g_norm, nrz = g_normz;
            double cnt = (double)g_count * (double)NUM_VV * 3.0;
            out[0] = (float)(sim / cnt);
            out[1] = (float)(nrm / (double)N * 0.5);
            out[2] = (float)(nrz / (double)N);
            g_sim = 0.0; g_norm = 0.0; g_normz = 0.0;
            g_count = 0ull; g_done = 0u;
        }
    }
}

// ---------------- launch -------------------------------------------------------
extern "C" void kernel_launch(void* const* d_in, const int* in_sizes, int n_in,
                              void* d_out, int out_size) {
    const float* ep   = (const float*)d_in[0];
    const float* K1   = (const float*)d_in[1];
    const float* K2   = (const float*)d_in[2];
    const float* E1   = (const float*)d_in[3];
    const float* E2   = (const float*)d_in[4];
    const float* rgb1 = (const float*)d_in[5];
    const float* rgb2 = (const float*)d_in[6];
    float* out = (float*)d_out;

    int N = in_sizes[0] / 12;

    repack_k<<<2048, 256>>>(rgb1, rgb2, K2, E1, E2);
    edge_k<<<N, 128>>>(ep, K1, out, N);
}

// round 11
// speedup vs baseline: 1.2124x; 1.0103x over previous
#include <cuda_runtime.h>
#include <math.h>

#define W_IMG 2000
#define H_IMG 1500
#define HW_IMG (W_IMG * H_IMG)
#define NUM_VV 10
#define EPSF 1e-6f

#define UMAXF (0.999999f * (float)(W_IMG - 1))
#define VMAXF (0.999999f * (float)(H_IMG - 1))

// ---------------- global accumulators (zero at load; last block re-zeros) ---
__device__ double g_sim;
__device__ double g_norm;
__device__ double g_normz;
__device__ unsigned long long g_count;
__device__ unsigned int g_done;
__device__ float g_T[12];

// ---------------- repacked images: pixel-pair u8 layout ---------------------
// entry (y, x): bytes [r0 g0 b0 r1 | g1 b1 0 0] for pixels (x, min(x+1,W-1))
__device__ uint2 g_p1[HW_IMG];
__device__ uint2 g_p2[HW_IMG];

// ---------------- register-only general 4x4 inverse (adjugate) --------------
__device__ __forceinline__ void inv4(const float m[16], float inv[16]) {
    inv[0] = m[5]*m[10]*m[15] - m[5]*m[11]*m[14] - m[9]*m[6]*m[15] + m[9]*m[7]*m[14] + m[13]*m[6]*m[11] - m[13]*m[7]*m[10];
    inv[4] = -m[4]*m[10]*m[15] + m[4]*m[11]*m[14] + m[8]*m[6]*m[15] - m[8]*m[7]*m[14] - m[12]*m[6]*m[11] + m[12]*m[7]*m[10];
    inv[8] = m[4]*m[9]*m[15] - m[4]*m[11]*m[13] - m[8]*m[5]*m[15] + m[8]*m[7]*m[13] + m[12]*m[5]*m[11] - m[12]*m[7]*m[9];
    inv[12] = -m[4]*m[9]*m[14] + m[4]*m[10]*m[13] + m[8]*m[5]*m[14] - m[8]*m[6]*m[13] - m[12]*m[5]*m[10] + m[12]*m[6]*m[9];
    inv[1] = -m[1]*m[10]*m[15] + m[1]*m[11]*m[14] + m[9]*m[2]*m[15] - m[9]*m[3]*m[14] - m[13]*m[2]*m[11] + m[13]*m[3]*m[10];
    inv[5] = m[0]*m[10]*m[15] - m[0]*m[11]*m[14] - m[8]*m[2]*m[15] + m[8]*m[3]*m[14] + m[12]*m[2]*m[11] - m[12]*m[3]*m[10];
    inv[9] = -m[0]*m[9]*m[15] + m[0]*m[11]*m[13] + m[8]*m[1]*m[15] - m[8]*m[3]*m[13] - m[12]*m[1]*m[11] + m[12]*m[3]*m[9];
    inv[13] = m[0]*m[9]*m[14] - m[0]*m[10]*m[13] - m[8]*m[1]*m[14] + m[8]*m[2]*m[13] + m[12]*m[1]*m[10] - m[12]*m[2]*m[9];
    inv[2] = m[1]*m[6]*m[15] - m[1]*m[7]*m[14] - m[5]*m[2]*m[15] + m[5]*m[3]*m[14] + m[13]*m[2]*m[7] - m[13]*m[3]*m[6];
    inv[6] = -m[0]*m[6]*m[15] + m[0]*m[7]*m[14] + m[4]*m[2]*m[15] - m[4]*m[3]*m[14] - m[12]*m[2]*m[7] + m[12]*m[3]*m[6];
    inv[10] = m[0]*m[5]*m[15] - m[0]*m[7]*m[13] - m[4]*m[1]*m[15] + m[4]*m[3]*m[13] + m[12]*m[1]*m[7] - m[12]*m[3]*m[5];
    inv[14] = -m[0]*m[5]*m[14] + m[0]*m[6]*m[13] + m[4]*m[1]*m[14] - m[4]*m[2]*m[13] - m[12]*m[1]*m[6] + m[12]*m[2]*m[5];
    inv[3] = -m[1]*m[6]*m[11] + m[1]*m[7]*m[10] + m[5]*m[2]*m[11] - m[5]*m[3]*m[10] - m[9]*m[2]*m[7] + m[9]*m[3]*m[6];
    inv[7] = m[0]*m[6]*m[11] - m[0]*m[7]*m[10] - m[4]*m[2]*m[11] + m[4]*m[3]*m[10] + m[8]*m[2]*m[7] - m[8]*m[3]*m[6];
    inv[11] = -m[0]*m[5]*m[11] + m[0]*m[7]*m[9] + m[4]*m[1]*m[11] - m[4]*m[3]*m[9] - m[8]*m[1]*m[7] + m[8]*m[3]*m[5];
    inv[15] = m[0]*m[5]*m[10] - m[0]*m[6]*m[9] - m[4]*m[1]*m[10] + m[4]*m[2]*m[9] + m[8]*m[1]*m[6] - m[8]*m[2]*m[5];
    float det = m[0]*inv[0] + m[1]*inv[4] + m[2]*inv[8] + m[3]*inv[12];
    float rd = 1.0f / det;
    #pragma unroll
    for (int i = 0; i < 16; i++) inv[i] *= rd;
}

// ---------------- repack kernel (also builds T once) -------------------------
__global__ void repack_k(const float* __restrict__ rgb1,
                         const float* __restrict__ rgb2,
                         const float* __restrict__ K2,
                         const float* __restrict__ E1,
                         const float* __restrict__ E2) {
    if (blockIdx.x == 0 && threadIdx.x == 0) {
        float m[16], iv[16];
        #pragma unroll
        for (int i = 0; i < 16; i++) m[i] = E1[i];
        inv4(m, iv);
        float Mm[12];
        #pragma unroll
        for (int i = 0; i < 3; i++)
            #pragma unroll
            for (int j = 0; j < 4; j++) {
                float s = 0.0f;
                #pragma unroll
                for (int k = 0; k < 4; k++) s += E2[i * 4 + k] * iv[k * 4 + j];
                Mm[i * 4 + j] = s;
            }
        #pragma unroll
        for (int i = 0; i < 3; i++)
            #pragma unroll
            for (int j = 0; j < 4; j++) {
                float s = 0.0f;
                #pragma unroll
                for (int k = 0; k < 3; k++) s += K2[i * 3 + k] * Mm[k * 4 + j];
                g_T[i * 4 + j] = s;
            }
    }

    int idx = blockIdx.x * blockDim.x + threadIdx.x;
    int stride = gridDim.x * blockDim.x;
    for (int i = idx; i < HW_IMG; i += stride) {
        int x = i % W_IMG;
        int ip1 = (x < W_IMG - 1) ? i + 1 : i;

        unsigned int r0 = __float2uint_rn(rgb1[i] * 255.0f);
        unsigned int gg0 = __float2uint_rn(rgb1[HW_IMG + i] * 255.0f);
        unsigned int b0 = __float2uint_rn(rgb1[2 * HW_IMG + i] * 255.0f);
        unsigned int r1 = __float2uint_rn(rgb1[ip1] * 255.0f);
        unsigned int gg1 = __float2uint_rn(rgb1[HW_IMG + ip1] * 255.0f);
        unsigned int b1 = __float2uint_rn(rgb1[2 * HW_IMG + ip1] * 255.0f);
        uint2 v;
        v.x = r0 | (gg0 << 8) | (b0 << 16) | (r1 << 24);
        v.y = gg1 | (b1 << 8);
        g_p1[i] = v;

        r0 = __float2uint_rn(rgb2[i] * 255.0f);
        gg0 = __float2uint_rn(rgb2[HW_IMG + i] * 255.0f);
        b0 = __float2uint_rn(rgb2[2 * HW_IMG + i] * 255.0f);
        r1 = __float2uint_rn(rgb2[ip1] * 255.0f);
        gg1 = __float2uint_rn(rgb2[HW_IMG + ip1] * 255.0f);
        b1 = __float2uint_rn(rgb2[2 * HW_IMG + ip1] * 255.0f);
        v.x = r0 | (gg0 << 8) | (b0 << 16) | (r1 << 24);
        v.y = gg1 | (b1 << 8);
        g_p2[i] = v;
    }
}

// ---------------- bilinear sample from u8 pixel pairs (pixel-space coords) --
__device__ __forceinline__ void sample3u(const uint2* __restrict__ img, float x, float y,
                                         float& c0, float& c1, float& c2) {
    float xf = floorf(x), yf = floorf(y);
    int x0 = (int)xf, y0 = (int)yf;
    int y1 = min(y0 + 1, H_IMG - 1);
    float wx = x - xf, wy = y - yf;

    uint2 qa = img[y0 * W_IMG + x0];   // row y0: pixels x0, x0+1
    uint2 qb = img[y1 * W_IMG + x0];   // row y1

    float ar0 = (float)(qa.x & 0xffu);
    float ag0 = (float)((qa.x >> 8) & 0xffu);
    float ab0 = (float)((qa.x >> 16) & 0xffu);
    float ar1 = (float)(qa.x >> 24);
    float ag1 = (float)(qa.y & 0xffu);
    float ab1 = (float)((qa.y >> 8) & 0xffu);

    float br0 = (float)(qb.x & 0xffu);
    float bg0 = (float)((qb.x >> 8) & 0xffu);
    float bb0 = (float)((qb.x >> 16) & 0xffu);
    float br1 = (float)(qb.x >> 24);
    float bg1 = (float)(qb.y & 0xffu);
    float bb1 = (float)((qb.y >> 8) & 0xffu);

    float tr = ar0 + wx * (ar1 - ar0);
    float tg = ag0 + wx * (ag1 - ag0);
    float tb = ab0 + wx * (ab1 - ab0);
    float br = br0 + wx * (br1 - br0);
    float bg = bg0 + wx * (bg1 - bg0);
    float bb = bb0 + wx * (bb1 - bb0);
    c0 = (tr + wy * (br - tr)) * (1.0f / 255.0f);
    c1 = (tg + wy * (bg - tg)) * (1.0f / 255.0f);
    c2 = (tb + wy * (bb - tb)) * (1.0f / 255.0f);
}

// ---------------- main per-edge kernel ---------------------------------------
__global__ __launch_bounds__(128) void edge_k(const float* __restrict__ ep,
                                              const float* __restrict__ K1,
                                              float* __restrict__ out,
                                              int N) {
    int e = blockIdx.x;
    if (e >= N) return;

    const float* p = ep + (size_t)e * 12;
    float p0x = p[0],  p0y = p[1],  p0z = p[2];
    float p1x = p[3],  p1y = p[4],  p1z = p[5];
    float p2x = p[6],  p2y = p[7],  p2z = p[8];
    float p3x = p[9],  p3y = p[10], p3z = p[11];

    float cdx = p1x - p0x, cdy = p1y - p0y, cdz = p1z - p0z;
    float ndx = p3x - p1x, ndy = p3y - p1y, ndz = p3z - p1z;

    float ax = cdx + EPSF, ay = cdy + EPSF, az = cdz + EPSF;
    float cur_len = sqrtf(ax * ax + ay * ay + az * az);
    float inv_len = 1.0f / cur_len;
    float dx = cdx * inv_len, dy_ = cdy * inv_len, dz = cdz * inv_len;

    float cnx = dy_ * ndz - dz * ndy;
    float cny = dz * ndx - dx * ndz;
    float cnz = dx * ndy - dy_ * ndx;
    {
        float nn = sqrtf(cnx * cnx + cny * cny + cnz * cnz) + EPSF;
        cnx /= nn; cny /= nn; cnz /= nn;
    }
    if (cnz > 0.0f) { cnx = -cnx; cny = -cny; cnz = -cnz; }

    float cux = cny * dz - cnz * dy_;
    float cuy = cnz * dx - cnx * dz;
    float cuz = cnx * dy_ - cny * dx;
    {
        float nn = sqrtf(cux * cux + cuy * cuy + cuz * cuz) + EPSF;
        cux /= nn; cuy /= nn; cuz /= nn;
    }

    int num_h = (int)floorf(cur_len / 0.05f);
    num_h = max(2, min(1000, num_h));

    if (threadIdx.x == 0) {
        float pdx = p0x - p2x, pdy = p0y - p2y, pdz = p0z - p2z;
        float pnx = pdy * dz - pdz * dy_;
        float pny = pdz * dx - pdx * dz;
        float pnz = pdx * dy_ - pdy * dx;
        float nn = sqrtf(pnx * pnx + pny * pny + pnz * pnz) + EPSF;
        float nl = 1.0f - (cnx * pnx + cny * pny + cnz * pnz) / nn;

        float onx = p0y * p1z - p0z * p1y;
        float ony = p0z * p1x - p0x * p1z;
        float onz = p0x * p1y - p0y * p1x;
        float on = sqrtf(onx * onx + ony * ony + onz * onz) + EPSF;
        float snp = fminf(fabsf((cux * onx + cuy * ony + cuz * onz) / on), 0.5f);
        float nz = 1.0f - snp / 0.5f;

        atomicAdd(&g_norm, (double)nl);
        atomicAdd(&g_normz, (double)nz);
        atomicAdd(&g_count, (unsigned long long)num_h);
    }

    // projection rows with (W-1)/(H-1) folded in -> pixel-space coordinates
    const float WS = (float)(W_IMG - 1), HS = (float)(H_IMG - 1);
    float k00 = K1[0] * WS, k01 = K1[1] * WS, k02 = K1[2] * WS;
    float k10 = K1[3] * HS, k11 = K1[4] * HS, k12 = K1[5] * HS;
    float k20 = K1[6],      k21 = K1[7],      k22 = K1[8];
    float t00 = g_T[0] * WS, t01 = g_T[1] * WS, t02 = g_T[2] * WS,  t03 = g_T[3] * WS;
    float t10 = g_T[4] * HS, t11 = g_T[5] * HS, t12 = g_T[6] * HS,  t13 = g_T[7] * HS;
    float t20 = g_T[8],      t21 = g_T[9],      t22 = g_T[10],      t23 = g_T[11];

    float step = cur_len / (float)(num_h - 1);
    int total = num_h * NUM_VV;
    double lsim = 0.0;

    for (int i = threadIdx.x; i < total; i += 128) {
        int px = i / NUM_VV;
        int dv = i - px * NUM_VV;
        float cx = (float)px * step;
        float cy = (float)dv * (0.5f / 9.0f);

        float ptx = dx * cx + cux * cy + p0x;
        float pty = dy_ * cx + cuy * cy + p0y;
        float ptz = dz * cx + cuz * cy + p0z;

        float z1 = k20 * ptx + k21 * pty + k22 * ptz;
        float rz1 = __fdividef(1.0f, z1);
        float x1 = fminf(fmaxf((k00 * ptx + k01 * pty + k02 * ptz) * rz1, 0.0f), UMAXF);
        float y1 = fminf(fmaxf((k10 * ptx + k11 * pty + k12 * ptz) * rz1, 0.0f), VMAXF);
        float s1a, s1b, s1c;
        sample3u(g_p1, x1, y1, s1a, s1b, s1c);

        float z2 = t20 * ptx + t21 * pty + t22 * ptz + t23;
        float rz2 = __fdividef(1.0f, z2);
        float x2 = fminf(fmaxf((t00 * ptx + t01 * pty + t02 * ptz + t03) * rz2, 0.0f), UMAXF);
        float y2 = fminf(fmaxf((t10 * ptx + t11 * pty + t12 * ptz + t13) * rz2, 0.0f), VMAXF);
        float s2a, s2b, s2c;
        sample3u(g_p2, x2, y2, s2a, s2b, s2c);

        float d0 = s1a - s2a, d1 = s1b - s2b, d2 = s1c - s2c;
        lsim += (double)(d0 * d0 + d1 * d1 + d2 * d2);
    }

    // block reduction
    for (int o = 16; o > 0; o >>= 1)
        lsim += __shfl_down_sync(0xffffffffu, lsim, o);
    __shared__ double ssum[4];
    int lane = threadIdx.x & 31;
    int w = threadIdx.x >> 5;
    if (lane == 0) ssum[w] = lsim;
    __syncthreads();
    if (threadIdx.x == 0) {
        double t = ssum[0] + ssum[1] + ssum[2] + ssum[3];
        atomicAdd(&g_sim, t);

        // last-block finalize
        __threadfence();
        unsigned int done = atomicAdd(&g_done, 1u);
        if (done == (unsigned int)gridDim.x - 1u) {
            double sim = g_sim, nrm = g_norm, nrz = g_normz;
            double cnt = (double)g_count * (double)NUM_VV * 3.0;
            out[0] = (float)(sim / cnt);
            out[1] = (float)(nrm / (double)N * 0.5);
            out[2] = (float)(nrz / (double)N);
            g_sim = 0.0; g_norm = 0.0; g_normz = 0.0;
            g_count = 0ull; g_done = 0u;
        }
    }
}

// ---------------- launch -------------------------------------------------------
extern "C" void kernel_launch(void* const* d_in, const int* in_sizes, int n_in,
                              void* d_out, int out_size) {
    const float* ep   = (const float*)d_in[0];
    const float* K1   = (const float*)d_in[1];
    const float* K2   = (const float*)d_in[2];
    const float* E1   = (const float*)d_in[3];
    const float* E2   = (const float*)d_in[4];
    const float* rgb1 = (const float*)d_in[5];
    const float* rgb2 = (const float*)d_in[6];
    float* out = (float*)d_out;

    int N = in_sizes[0] / 12;

    repack_k<<<2048, 256>>>(rgb1, rgb2, K2, E1, E2);
    edge_k<<<N, 128>>>(ep, K1, out, N);
}